// round 10
// baseline (speedup 1.0000x reference)
#include <cuda_runtime.h>
#include <math.h>

#define KM 16
#define DM 16
#define SPT 14          // samples per thread: one NP=4 batch + one NP=3 batch

typedef unsigned int u32;
typedef unsigned long long u64;

__device__ __forceinline__ u64 fma2(u64 a, u64 b, u64 c) {
    u64 r;
    asm("fma.rn.f32x2 %0, %1, %2, %3;" : "=l"(r) : "l"(a), "l"(b), "l"(c));
    return r;
}
__device__ __forceinline__ u64 pack2(float lo, float hi) {
    u64 r;
    asm("mov.b64 %0, {%1, %2};" : "=l"(r) : "f"(lo), "f"(hi));
    return r;
}
__device__ __forceinline__ void unpack2(u64 v, float& lo, float& hi) {
    asm("mov.b64 {%0, %1}, %2;" : "=f"(lo), "=f"(hi) : "l"(v));
}

// Shared-memory union: precompute scratch overlays the packed main tables.
union __align__(16) SU {
    struct {
        float L [KM][DM][DM + 1];
        float Mi[KM][DM][DM + 1];
    } pre;                                  // 34816 B
    struct {
        u64 M2[KM][DM][DM];                 // duplicated (m,m); zeros above diag
        u64 V2[KM][DM];                     // duplicated (-v,-v)
    } mc;                                   // 34816 B
};

// ---------------------------------------------------------------------------
// Packed-pair batch: 2*NP samples through the k-loop. Exact row lengths:
// pairs via LDS.128; even-i rows add one LDS.64 diagonal term (no pad FMA).
// out stores are float2 (base always even, never 16B-aligned guaranteed).
// ---------------------------------------------------------------------------
template <int NP>
__device__ __forceinline__ void process_batch(const float4* __restrict__ samples4,
                                              float* __restrict__ out,
                                              long base, const SU& su,
                                              const float* sC) {
    u64 d2[NP][DM];
    #pragma unroll
    for (int p = 0; p < NP; p++) {
        float r0[DM], r1[DM];
        #pragma unroll
        for (int q = 0; q < 4; q++) {
            float4 a = samples4[(base + 2 * p) * 4 + q];
            r0[4*q+0] = a.x; r0[4*q+1] = a.y; r0[4*q+2] = a.z; r0[4*q+3] = a.w;
            float4 b = samples4[(base + 2 * p + 1) * 4 + q];
            r1[4*q+0] = b.x; r1[4*q+1] = b.y; r1[4*q+2] = b.z; r1[4*q+3] = b.w;
        }
        #pragma unroll
        for (int j = 0; j < DM; j++) d2[p][j] = pack2(r0[j], r1[j]);
    }

    float pdf[2 * NP];
    #pragma unroll
    for (int s = 0; s < 2 * NP; s++) pdf[s] = 0.0f;

    #pragma unroll 1
    for (int k = 0; k < KM; k++) {
        u64 q2[NP];
        #pragma unroll
        for (int p = 0; p < NP; p++) q2[p] = 0ull;

        #pragma unroll
        for (int i = 0; i < DM; i++) {
            u64 z[NP];
            u64 v0 = su.mc.V2[k][i];
            #pragma unroll
            for (int p = 0; p < NP; p++) z[p] = v0;

            const int npairs = (i + 1) >> 1;        // full (j, j+1) pairs
            #pragma unroll
            for (int jp = 0; jp < npairs; jp++) {
                const int j = jp * 2;
                ulonglong2 m2 = *(const ulonglong2*)&su.mc.M2[k][i][j];
                #pragma unroll
                for (int p = 0; p < NP; p++) {
                    z[p] = fma2(m2.x, d2[p][j],     z[p]);
                    z[p] = fma2(m2.y, d2[p][j + 1], z[p]);
                }
            }
            if ((i & 1) == 0) {                     // odd row length: diagonal
                u64 md = su.mc.M2[k][i][i];
                #pragma unroll
                for (int p = 0; p < NP; p++)
                    z[p] = fma2(md, d2[p][i], z[p]);
            }
            #pragma unroll
            for (int p = 0; p < NP; p++) q2[p] = fma2(z[p], z[p], q2[p]);
        }

        float c = sC[k];
        #pragma unroll
        for (int p = 0; p < NP; p++) {
            float qa, qb;
            unpack2(q2[p], qa, qb);
            pdf[2*p + 0] += c * __expf(-0.5f * qa);
            pdf[2*p + 1] += c * __expf(-0.5f * qb);
        }
    }

    #pragma unroll
    for (int p = 0; p < NP; p++) {
        float2 o;
        o.x = -__logf(pdf[2*p + 0]);
        o.y = -__logf(pdf[2*p + 1]);
        *(float2*)&out[base + 2 * p] = o;
    }
}

// ---------------------------------------------------------------------------
// Fused kernel: per-block coefficient prologue + balanced 14-sample batches.
// ---------------------------------------------------------------------------
__global__ __launch_bounds__(256, 1)
void gmm_fused(const float4* __restrict__ samples4,
               const float* __restrict__ samples,
               const float* __restrict__ Phi,
               const float* __restrict__ mu,
               const float* __restrict__ Sigma,
               float* __restrict__ out, int N) {
    __shared__ SU su;
    __shared__ float sC[KM];

    const int tid  = threadIdx.x;
    const int wid  = tid >> 5;
    const int lane = tid & 31;
    const int k    = wid * 2 + (lane >> 4);   // 8 warps x 2 mixtures
    const int r    = lane & 15;

    // ---- Prologue: Cholesky + triangular inverse, 2 mixtures per warp ----
    for (int j = 0; j < DM; j++)
        su.pre.L[k][r][j] = Sigma[(k * DM + r) * DM + j];
    __syncwarp();

    for (int p = 0; p < DM; p++) {
        if (r == p) {
            float s = su.pre.L[k][p][p];
            for (int q = 0; q < p; q++) s -= su.pre.L[k][p][q] * su.pre.L[k][p][q];
            su.pre.L[k][p][p] = sqrtf(s);
        }
        __syncwarp();
        if (r > p) {
            float s = su.pre.L[k][r][p];
            for (int q = 0; q < p; q++) s -= su.pre.L[k][r][q] * su.pre.L[k][p][q];
            su.pre.L[k][r][p] = s / su.pre.L[k][p][p];
        }
        __syncwarp();
    }

    // Mi = L^{-1}: lane r computes column r.
    {
        int c = r;
        for (int i = 0; i < c; i++) su.pre.Mi[k][i][c] = 0.0f;
        su.pre.Mi[k][c][c] = 1.0f / su.pre.L[k][c][c];
        for (int i = c + 1; i < DM; i++) {
            float s = 0.0f;
            for (int q = c; q < i; q++) s += su.pre.L[k][i][q] * su.pre.Mi[k][q][c];
            su.pre.Mi[k][i][c] = -s / su.pre.L[k][i][i];
        }
    }
    __syncwarp();

    // Pull row r of Mi into registers; compute v_r; lane 0 computes the norm.
    float mrow[DM];
    for (int j = 0; j < DM; j++)
        mrow[j] = (j <= r) ? su.pre.Mi[k][r][j] : 0.0f;
    float v = 0.0f;
    for (int j = 0; j <= r; j++) v += mrow[j] * mu[k * DM + j];
    if (r == 0) {
        float prodL = 1.0f;
        for (int i = 0; i < DM; i++) prodL *= su.pre.L[k][i][i];   // sqrt(det)
        sC[k] = Phi[k] / (sqrtf(2.0f * 3.14159265358979323846f) * prodL);
    }
    __syncthreads();

    // Transcribe into packed main tables (overlays the prologue scratch).
    for (int j = 0; j < DM; j++)
        su.mc.M2[k][r][j] = pack2(mrow[j], mrow[j]);
    su.mc.V2[k][r] = pack2(-v, -v);
    __syncthreads();

    // ---- Main: 14 samples per thread = NP4 + NP3 ----
    long t = (long)blockIdx.x * blockDim.x + tid;
    long base = t * SPT;
    if (base >= N) return;

    if (base + SPT <= N) {
        process_batch<4>(samples4, out, base,     su, sC);
        process_batch<3>(samples4, out, base + 8, su, sC);
    } else {
        for (long n = base; n < N; n++) {
            float d[DM];
            for (int j = 0; j < DM; j++) d[j] = samples[n * DM + j];
            float pdf = 0.0f;
            for (int kk = 0; kk < KM; kk++) {
                float quad = 0.0f;
                for (int i = 0; i < DM; i++) {
                    // V2 holds (-v, -v): use element directly (no negation).
                    float z = ((const float*)&su.mc.V2[kk][i])[0];
                    for (int j = 0; j <= i; j++)
                        z = fmaf(((const float*)&su.mc.M2[kk][i][j])[0], d[j], z);
                    quad = fmaf(z, z, quad);
                }
                pdf += sC[kk] * __expf(-0.5f * quad);
            }
            out[n] = -logf(pdf);
        }
    }
}

// ---------------------------------------------------------------------------
extern "C" void kernel_launch(void* const* d_in, const int* in_sizes, int n_in,
                              void* d_out, int out_size) {
    const float* samples = (const float*)d_in[0];
    const float* Phi     = (const float*)d_in[1];
    const float* mu      = (const float*)d_in[2];
    const float* Sigma   = (const float*)d_in[3];
    int N = in_sizes[0] / DM;

    long threads = ((long)N + SPT - 1) / SPT;
    int  blocks  = (int)((threads + 255) / 256);
    gmm_fused<<<blocks, 256>>>((const float4*)samples, samples,
                               Phi, mu, Sigma, (float*)d_out, N);
}

// round 11
// speedup vs baseline: 1.1160x; 1.1160x over previous
#include <cuda_runtime.h>
#include <math.h>

#define KM 16
#define DM 16
#define SPT 14          // samples per thread: one NP=4 batch + one NP=3 batch

typedef unsigned int u32;
typedef unsigned long long u64;

__device__ __forceinline__ u64 fma2(u64 a, u64 b, u64 c) {
    u64 r;
    asm("fma.rn.f32x2 %0, %1, %2, %3;" : "=l"(r) : "l"(a), "l"(b), "l"(c));
    return r;
}
__device__ __forceinline__ u64 pack2(float lo, float hi) {
    u64 r;
    asm("mov.b64 %0, {%1, %2};" : "=l"(r) : "f"(lo), "f"(hi));
    return r;
}
__device__ __forceinline__ void unpack2(u64 v, float& lo, float& hi) {
    asm("mov.b64 {%0, %1}, %2;" : "=f"(lo), "=f"(hi) : "l"(v));
}

// Shared-memory union: precompute scratch overlays the packed main tables.
union __align__(16) SU {
    struct {
        float L [KM][DM][DM + 1];
        float Mi[KM][DM][DM + 1];
    } pre;                                  // 34816 B
    struct {
        u64 M2[KM][DM][DM];                 // duplicated (m,m); zeros above diag
        u64 V2[KM][DM];                     // duplicated (-v,-v)
    } mc;                                   // 34816 B
};

// ---------------------------------------------------------------------------
// Packed-pair batch: 2*NP samples, TWO mixtures (k, k+1) interleaved through
// the shared row loop -> 2*NP independent FMA chains per row.
// ---------------------------------------------------------------------------
template <int NP>
__device__ __forceinline__ void process_batch(const float4* __restrict__ samples4,
                                              float* __restrict__ out,
                                              long base, const SU& su,
                                              const float* sC) {
    u64 d2[NP][DM];
    #pragma unroll
    for (int p = 0; p < NP; p++) {
        float r0[DM], r1[DM];
        #pragma unroll
        for (int q = 0; q < 4; q++) {
            float4 a = samples4[(base + 2 * p) * 4 + q];
            r0[4*q+0] = a.x; r0[4*q+1] = a.y; r0[4*q+2] = a.z; r0[4*q+3] = a.w;
            float4 b = samples4[(base + 2 * p + 1) * 4 + q];
            r1[4*q+0] = b.x; r1[4*q+1] = b.y; r1[4*q+2] = b.z; r1[4*q+3] = b.w;
        }
        #pragma unroll
        for (int j = 0; j < DM; j++) d2[p][j] = pack2(r0[j], r1[j]);
    }

    float pdf[2 * NP];
    #pragma unroll
    for (int s = 0; s < 2 * NP; s++) pdf[s] = 0.0f;

    #pragma unroll 1
    for (int k = 0; k < KM; k += 2) {
        u64 qA[NP], qB[NP];
        #pragma unroll
        for (int p = 0; p < NP; p++) { qA[p] = 0ull; qB[p] = 0ull; }

        #pragma unroll
        for (int i = 0; i < DM; i++) {
            u64 zA[NP], zB[NP];
            u64 vA = su.mc.V2[k][i];
            u64 vB = su.mc.V2[k + 1][i];
            #pragma unroll
            for (int p = 0; p < NP; p++) { zA[p] = vA; zB[p] = vB; }

            const int npairs = (i + 1) >> 1;        // full (j, j+1) pairs
            #pragma unroll
            for (int jp = 0; jp < npairs; jp++) {
                const int j = jp * 2;
                ulonglong2 mA = *(const ulonglong2*)&su.mc.M2[k][i][j];
                ulonglong2 mB = *(const ulonglong2*)&su.mc.M2[k + 1][i][j];
                #pragma unroll
                for (int p = 0; p < NP; p++) {
                    zA[p] = fma2(mA.x, d2[p][j],     zA[p]);
                    zB[p] = fma2(mB.x, d2[p][j],     zB[p]);
                    zA[p] = fma2(mA.y, d2[p][j + 1], zA[p]);
                    zB[p] = fma2(mB.y, d2[p][j + 1], zB[p]);
                }
            }
            if ((i & 1) == 0) {                     // odd row length: diagonal
                u64 mdA = su.mc.M2[k][i][i];
                u64 mdB = su.mc.M2[k + 1][i][i];
                #pragma unroll
                for (int p = 0; p < NP; p++) {
                    zA[p] = fma2(mdA, d2[p][i], zA[p]);
                    zB[p] = fma2(mdB, d2[p][i], zB[p]);
                }
            }
            #pragma unroll
            for (int p = 0; p < NP; p++) {
                qA[p] = fma2(zA[p], zA[p], qA[p]);
                qB[p] = fma2(zB[p], zB[p], qB[p]);
            }
        }

        float cA = sC[k];
        float cB = sC[k + 1];
        #pragma unroll
        for (int p = 0; p < NP; p++) {
            float a0, a1, b0, b1;
            unpack2(qA[p], a0, a1);
            unpack2(qB[p], b0, b1);
            pdf[2*p + 0] += cA * __expf(-0.5f * a0) + cB * __expf(-0.5f * b0);
            pdf[2*p + 1] += cA * __expf(-0.5f * a1) + cB * __expf(-0.5f * b1);
        }
    }

    #pragma unroll
    for (int p = 0; p < NP; p++) {
        float2 o;
        o.x = -__logf(pdf[2*p + 0]);
        o.y = -__logf(pdf[2*p + 1]);
        *(float2*)&out[base + 2 * p] = o;
    }
}

// ---------------------------------------------------------------------------
// Fused kernel: per-block coefficient prologue + balanced 14-sample batches.
// ---------------------------------------------------------------------------
__global__ __launch_bounds__(256, 1)
void gmm_fused(const float4* __restrict__ samples4,
               const float* __restrict__ samples,
               const float* __restrict__ Phi,
               const float* __restrict__ mu,
               const float* __restrict__ Sigma,
               float* __restrict__ out, int N) {
    __shared__ SU su;
    __shared__ float sC[KM];

    const int tid  = threadIdx.x;
    const int wid  = tid >> 5;
    const int lane = tid & 31;
    const int k    = wid * 2 + (lane >> 4);   // 8 warps x 2 mixtures
    const int r    = lane & 15;

    // ---- Prologue: Cholesky + triangular inverse, 2 mixtures per warp ----
    for (int j = 0; j < DM; j++)
        su.pre.L[k][r][j] = Sigma[(k * DM + r) * DM + j];
    __syncwarp();

    for (int p = 0; p < DM; p++) {
        if (r == p) {
            float s = su.pre.L[k][p][p];
            for (int q = 0; q < p; q++) s -= su.pre.L[k][p][q] * su.pre.L[k][p][q];
            su.pre.L[k][p][p] = sqrtf(s);
        }
        __syncwarp();
        if (r > p) {
            float s = su.pre.L[k][r][p];
            for (int q = 0; q < p; q++) s -= su.pre.L[k][r][q] * su.pre.L[k][p][q];
            su.pre.L[k][r][p] = s / su.pre.L[k][p][p];
        }
        __syncwarp();
    }

    // Mi = L^{-1}: lane r computes column r.
    {
        int c = r;
        for (int i = 0; i < c; i++) su.pre.Mi[k][i][c] = 0.0f;
        su.pre.Mi[k][c][c] = 1.0f / su.pre.L[k][c][c];
        for (int i = c + 1; i < DM; i++) {
            float s = 0.0f;
            for (int q = c; q < i; q++) s += su.pre.L[k][i][q] * su.pre.Mi[k][q][c];
            su.pre.Mi[k][i][c] = -s / su.pre.L[k][i][i];
        }
    }
    __syncwarp();

    // Pull row r of Mi into registers; compute v_r; lane 0 computes the norm.
    float mrow[DM];
    for (int j = 0; j < DM; j++)
        mrow[j] = (j <= r) ? su.pre.Mi[k][r][j] : 0.0f;
    float v = 0.0f;
    for (int j = 0; j <= r; j++) v += mrow[j] * mu[k * DM + j];
    if (r == 0) {
        float prodL = 1.0f;
        for (int i = 0; i < DM; i++) prodL *= su.pre.L[k][i][i];   // sqrt(det)
        sC[k] = Phi[k] / (sqrtf(2.0f * 3.14159265358979323846f) * prodL);
    }
    __syncthreads();

    // Transcribe into packed main tables (overlays the prologue scratch).
    for (int j = 0; j < DM; j++)
        su.mc.M2[k][r][j] = pack2(mrow[j], mrow[j]);
    su.mc.V2[k][r] = pack2(-v, -v);
    __syncthreads();

    // ---- Main: 14 samples per thread = NP4 + NP3 ----
    long t = (long)blockIdx.x * blockDim.x + tid;
    long base = t * SPT;
    if (base >= N) return;

    if (base + SPT <= N) {
        process_batch<4>(samples4, out, base,     su, sC);
        process_batch<3>(samples4, out, base + 8, su, sC);
    } else {
        for (long n = base; n < N; n++) {
            float d[DM];
            for (int j = 0; j < DM; j++) d[j] = samples[n * DM + j];
            float pdf = 0.0f;
            for (int kk = 0; kk < KM; kk++) {
                float quad = 0.0f;
                for (int i = 0; i < DM; i++) {
                    // V2 holds (-v, -v): use element directly (no negation).
                    float z = ((const float*)&su.mc.V2[kk][i])[0];
                    for (int j = 0; j <= i; j++)
                        z = fmaf(((const float*)&su.mc.M2[kk][i][j])[0], d[j], z);
                    quad = fmaf(z, z, quad);
                }
                pdf += sC[kk] * __expf(-0.5f * quad);
            }
            out[n] = -logf(pdf);
        }
    }
}

// ---------------------------------------------------------------------------
extern "C" void kernel_launch(void* const* d_in, const int* in_sizes, int n_in,
                              void* d_out, int out_size) {
    const float* samples = (const float*)d_in[0];
    const float* Phi     = (const float*)d_in[1];
    const float* mu      = (const float*)d_in[2];
    const float* Sigma   = (const float*)d_in[3];
    int N = in_sizes[0] / DM;

    long threads = ((long)N + SPT - 1) / SPT;
    int  blocks  = (int)((threads + 255) / 256);
    gmm_fused<<<blocks, 256>>>((const float4*)samples, samples,
                               Phi, mu, Sigma, (float*)d_out, N);
}

// round 12
// speedup vs baseline: 1.1478x; 1.0285x over previous
#include <cuda_runtime.h>
#include <math.h>

#define KM 16
#define DM 16
#define SPT 14          // samples per thread: one NP=4 batch + one NP=3 batch

typedef unsigned int u32;
typedef unsigned long long u64;

__device__ __forceinline__ u64 fma2(u64 a, u64 b, u64 c) {
    u64 r;
    asm("fma.rn.f32x2 %0, %1, %2, %3;" : "=l"(r) : "l"(a), "l"(b), "l"(c));
    return r;
}
__device__ __forceinline__ u64 pack2(float lo, float hi) {
    u64 r;
    asm("mov.b64 %0, {%1, %2};" : "=l"(r) : "f"(lo), "f"(hi));
    return r;
}
__device__ __forceinline__ void unpack2(u64 v, float& lo, float& hi) {
    asm("mov.b64 {%0, %1}, %2;" : "=f"(lo), "=f"(hi) : "l"(v));
}

// Shared-memory union: precompute scratch overlays the packed main tables.
union __align__(16) SU {
    struct {
        float L [KM][DM][DM + 1];
        float Mi[KM][DM][DM + 1];
    } pre;                                  // 34816 B
    struct {
        u64 M2[KM][DM][DM];                 // duplicated (m,m); zeros above diag
        u64 V2[KM][DM];                     // duplicated (-v,-v)
    } mc;                                   // 34816 B
};

// ---------------------------------------------------------------------------
// Packed-pair batch: 2*NP samples, two mixtures (k, k+1) interleaved, with
// one-row-ahead software prefetch of each row's head (V2 + first pair).
// ---------------------------------------------------------------------------
template <int NP>
__device__ __forceinline__ void process_batch(const float4* __restrict__ samples4,
                                              float* __restrict__ out,
                                              long base, const SU& su,
                                              const float* sC) {
    u64 d2[NP][DM];
    #pragma unroll
    for (int p = 0; p < NP; p++) {
        float r0[DM], r1[DM];
        #pragma unroll
        for (int q = 0; q < 4; q++) {
            float4 a = samples4[(base + 2 * p) * 4 + q];
            r0[4*q+0] = a.x; r0[4*q+1] = a.y; r0[4*q+2] = a.z; r0[4*q+3] = a.w;
            float4 b = samples4[(base + 2 * p + 1) * 4 + q];
            r1[4*q+0] = b.x; r1[4*q+1] = b.y; r1[4*q+2] = b.z; r1[4*q+3] = b.w;
        }
        #pragma unroll
        for (int j = 0; j < DM; j++) d2[p][j] = pack2(r0[j], r1[j]);
    }

    float pdf[2 * NP];
    #pragma unroll
    for (int s = 0; s < 2 * NP; s++) pdf[s] = 0.0f;

    #pragma unroll 1
    for (int k = 0; k < KM; k += 2) {
        u64 qA[NP], qB[NP];
        #pragma unroll
        for (int p = 0; p < NP; p++) { qA[p] = 0ull; qB[p] = 0ull; }

        // ---- Row 0 (diag only), with inline loads ----
        {
            u64 vA  = su.mc.V2[k][0];
            u64 vB  = su.mc.V2[k + 1][0];
            u64 mdA = su.mc.M2[k][0][0];
            u64 mdB = su.mc.M2[k + 1][0][0];
            #pragma unroll
            for (int p = 0; p < NP; p++) {
                u64 zA = fma2(mdA, d2[p][0], vA);
                u64 zB = fma2(mdB, d2[p][0], vB);
                qA[p] = fma2(zA, zA, qA[p]);
                qB[p] = fma2(zB, zB, qB[p]);
            }
        }

        // ---- Prefetch head of row 1 ----
        u64 nvA = su.mc.V2[k][1];
        u64 nvB = su.mc.V2[k + 1][1];
        ulonglong2 npA = *(const ulonglong2*)&su.mc.M2[k][1][0];
        ulonglong2 npB = *(const ulonglong2*)&su.mc.M2[k + 1][1][0];

        #pragma unroll
        for (int i = 1; i < DM; i++) {
            // Consume this row's prefetched head.
            u64 cvA = nvA, cvB = nvB;
            ulonglong2 cpA = npA, cpB = npB;

            // Prefetch next row's head (V2 + first pair).
            if (i + 1 < DM) {
                nvA = su.mc.V2[k][i + 1];
                nvB = su.mc.V2[k + 1][i + 1];
                npA = *(const ulonglong2*)&su.mc.M2[k][i + 1][0];
                npB = *(const ulonglong2*)&su.mc.M2[k + 1][i + 1][0];
            }

            u64 zA[NP], zB[NP];
            #pragma unroll
            for (int p = 0; p < NP; p++) { zA[p] = cvA; zB[p] = cvB; }

            // First pair from the prefetch registers.
            #pragma unroll
            for (int p = 0; p < NP; p++) {
                zA[p] = fma2(cpA.x, d2[p][0], zA[p]);
                zB[p] = fma2(cpB.x, d2[p][0], zB[p]);
                zA[p] = fma2(cpA.y, d2[p][1], zA[p]);
                zB[p] = fma2(cpB.y, d2[p][1], zB[p]);
            }

            // Remaining pairs: inline LDS.128 loads.
            const int npairs = (i + 1) >> 1;
            #pragma unroll
            for (int jp = 1; jp < npairs; jp++) {
                const int j = jp * 2;
                ulonglong2 mA = *(const ulonglong2*)&su.mc.M2[k][i][j];
                ulonglong2 mB = *(const ulonglong2*)&su.mc.M2[k + 1][i][j];
                #pragma unroll
                for (int p = 0; p < NP; p++) {
                    zA[p] = fma2(mA.x, d2[p][j],     zA[p]);
                    zB[p] = fma2(mB.x, d2[p][j],     zB[p]);
                    zA[p] = fma2(mA.y, d2[p][j + 1], zA[p]);
                    zB[p] = fma2(mB.y, d2[p][j + 1], zB[p]);
                }
            }
            if ((i & 1) == 0) {                     // odd row length: diagonal
                u64 mdA = su.mc.M2[k][i][i];
                u64 mdB = su.mc.M2[k + 1][i][i];
                #pragma unroll
                for (int p = 0; p < NP; p++) {
                    zA[p] = fma2(mdA, d2[p][i], zA[p]);
                    zB[p] = fma2(mdB, d2[p][i], zB[p]);
                }
            }
            #pragma unroll
            for (int p = 0; p < NP; p++) {
                qA[p] = fma2(zA[p], zA[p], qA[p]);
                qB[p] = fma2(zB[p], zB[p], qB[p]);
            }
        }

        float cA = sC[k];
        float cB = sC[k + 1];
        #pragma unroll
        for (int p = 0; p < NP; p++) {
            float a0, a1, b0, b1;
            unpack2(qA[p], a0, a1);
            unpack2(qB[p], b0, b1);
            pdf[2*p + 0] += cA * __expf(-0.5f * a0) + cB * __expf(-0.5f * b0);
            pdf[2*p + 1] += cA * __expf(-0.5f * a1) + cB * __expf(-0.5f * b1);
        }
    }

    #pragma unroll
    for (int p = 0; p < NP; p++) {
        float2 o;
        o.x = -__logf(pdf[2*p + 0]);
        o.y = -__logf(pdf[2*p + 1]);
        *(float2*)&out[base + 2 * p] = o;
    }
}

// ---------------------------------------------------------------------------
// Fused kernel: per-block coefficient prologue + balanced 14-sample batches.
// ---------------------------------------------------------------------------
__global__ __launch_bounds__(256, 1)
void gmm_fused(const float4* __restrict__ samples4,
               const float* __restrict__ samples,
               const float* __restrict__ Phi,
               const float* __restrict__ mu,
               const float* __restrict__ Sigma,
               float* __restrict__ out, int N) {
    __shared__ SU su;
    __shared__ float sC[KM];

    const int tid  = threadIdx.x;
    const int wid  = tid >> 5;
    const int lane = tid & 31;
    const int k    = wid * 2 + (lane >> 4);   // 8 warps x 2 mixtures
    const int r    = lane & 15;

    // ---- Prologue: Cholesky + triangular inverse, 2 mixtures per warp ----
    for (int j = 0; j < DM; j++)
        su.pre.L[k][r][j] = Sigma[(k * DM + r) * DM + j];
    __syncwarp();

    for (int p = 0; p < DM; p++) {
        if (r == p) {
            float s = su.pre.L[k][p][p];
            for (int q = 0; q < p; q++) s -= su.pre.L[k][p][q] * su.pre.L[k][p][q];
            su.pre.L[k][p][p] = sqrtf(s);
        }
        __syncwarp();
        if (r > p) {
            float s = su.pre.L[k][r][p];
            for (int q = 0; q < p; q++) s -= su.pre.L[k][r][q] * su.pre.L[k][p][q];
            su.pre.L[k][r][p] = s / su.pre.L[k][p][p];
        }
        __syncwarp();
    }

    // Mi = L^{-1}: lane r computes column r.
    {
        int c = r;
        for (int i = 0; i < c; i++) su.pre.Mi[k][i][c] = 0.0f;
        su.pre.Mi[k][c][c] = 1.0f / su.pre.L[k][c][c];
        for (int i = c + 1; i < DM; i++) {
            float s = 0.0f;
            for (int q = c; q < i; q++) s += su.pre.L[k][i][q] * su.pre.Mi[k][q][c];
            su.pre.Mi[k][i][c] = -s / su.pre.L[k][i][i];
        }
    }
    __syncwarp();

    // Pull row r of Mi into registers; compute v_r; lane 0 computes the norm.
    float mrow[DM];
    for (int j = 0; j < DM; j++)
        mrow[j] = (j <= r) ? su.pre.Mi[k][r][j] : 0.0f;
    float v = 0.0f;
    for (int j = 0; j <= r; j++) v += mrow[j] * mu[k * DM + j];
    if (r == 0) {
        float prodL = 1.0f;
        for (int i = 0; i < DM; i++) prodL *= su.pre.L[k][i][i];   // sqrt(det)
        sC[k] = Phi[k] / (sqrtf(2.0f * 3.14159265358979323846f) * prodL);
    }
    __syncthreads();

    // Transcribe into packed main tables (overlays the prologue scratch).
    for (int j = 0; j < DM; j++)
        su.mc.M2[k][r][j] = pack2(mrow[j], mrow[j]);
    su.mc.V2[k][r] = pack2(-v, -v);
    __syncthreads();

    // ---- Main: 14 samples per thread = NP4 + NP3 ----
    long t = (long)blockIdx.x * blockDim.x + tid;
    long base = t * SPT;
    if (base >= N) return;

    if (base + SPT <= N) {
        process_batch<4>(samples4, out, base,     su, sC);
        process_batch<3>(samples4, out, base + 8, su, sC);
    } else {
        for (long n = base; n < N; n++) {
            float d[DM];
            for (int j = 0; j < DM; j++) d[j] = samples[n * DM + j];
            float pdf = 0.0f;
            for (int kk = 0; kk < KM; kk++) {
                float quad = 0.0f;
                for (int i = 0; i < DM; i++) {
                    // V2 holds (-v, -v): use element directly (no negation).
                    float z = ((const float*)&su.mc.V2[kk][i])[0];
                    for (int j = 0; j <= i; j++)
                        z = fmaf(((const float*)&su.mc.M2[kk][i][j])[0], d[j], z);
                    quad = fmaf(z, z, quad);
                }
                pdf += sC[kk] * __expf(-0.5f * quad);
            }
            out[n] = -logf(pdf);
        }
    }
}

// ---------------------------------------------------------------------------
extern "C" void kernel_launch(void* const* d_in, const int* in_sizes, int n_in,
                              void* d_out, int out_size) {
    const float* samples = (const float*)d_in[0];
    const float* Phi     = (const float*)d_in[1];
    const float* mu      = (const float*)d_in[2];
    const float* Sigma   = (const float*)d_in[3];
    int N = in_sizes[0] / DM;

    long threads = ((long)N + SPT - 1) / SPT;
    int  blocks  = (int)((threads + 255) / 256);
    gmm_fused<<<blocks, 256>>>((const float4*)samples, samples,
                               Phi, mu, Sigma, (float*)d_out, N);
}

// round 13
// speedup vs baseline: 1.1555x; 1.0067x over previous
#include <cuda_runtime.h>
#include <math.h>

#define KM 16
#define DM 16
#define SPT 14          // samples per thread: one NP=4 batch + one NP=3 batch

typedef unsigned int u32;
typedef unsigned long long u64;

__device__ __forceinline__ u64 fma2(u64 a, u64 b, u64 c) {
    u64 r;
    asm("fma.rn.f32x2 %0, %1, %2, %3;" : "=l"(r) : "l"(a), "l"(b), "l"(c));
    return r;
}
__device__ __forceinline__ u64 pack2(float lo, float hi) {
    u64 r;
    asm("mov.b64 %0, {%1, %2};" : "=l"(r) : "f"(lo), "f"(hi));
    return r;
}
__device__ __forceinline__ void unpack2(u64 v, float& lo, float& hi) {
    asm("mov.b64 {%0, %1}, %2;" : "=f"(lo), "=f"(hi) : "l"(v));
}

// Shared-memory union: precompute scratch overlays the packed main tables.
union __align__(16) SU {
    struct {
        float L [KM][DM][DM + 1];
        float Mi[KM][DM][DM + 1];
    } pre;                                  // 34816 B
    struct {
        u64 M2[KM][DM][DM];                 // duplicated (m,m); zeros above diag
        u64 V2[KM][DM];                     // duplicated (-v,-v)
    } mc;                                   // 34816 B
};

// ---------------------------------------------------------------------------
// Packed-pair batch: 2*NP samples, two mixtures (k, k+1) interleaved, with
// one-row-ahead software prefetch of each row's head (V2 + first pair).
// ---------------------------------------------------------------------------
template <int NP>
__device__ __forceinline__ void process_batch(const float4* __restrict__ samples4,
                                              float* __restrict__ out,
                                              long base, const SU& su,
                                              const float* sC) {
    u64 d2[NP][DM];
    #pragma unroll
    for (int p = 0; p < NP; p++) {
        float r0[DM], r1[DM];
        #pragma unroll
        for (int q = 0; q < 4; q++) {
            float4 a = samples4[(base + 2 * p) * 4 + q];
            r0[4*q+0] = a.x; r0[4*q+1] = a.y; r0[4*q+2] = a.z; r0[4*q+3] = a.w;
            float4 b = samples4[(base + 2 * p + 1) * 4 + q];
            r1[4*q+0] = b.x; r1[4*q+1] = b.y; r1[4*q+2] = b.z; r1[4*q+3] = b.w;
        }
        #pragma unroll
        for (int j = 0; j < DM; j++) d2[p][j] = pack2(r0[j], r1[j]);
    }

    float pdf[2 * NP];
    #pragma unroll
    for (int s = 0; s < 2 * NP; s++) pdf[s] = 0.0f;

    #pragma unroll 1
    for (int k = 0; k < KM; k += 2) {
        u64 qA[NP], qB[NP];
        #pragma unroll
        for (int p = 0; p < NP; p++) { qA[p] = 0ull; qB[p] = 0ull; }

        // ---- Row 0 (diag only), with inline loads ----
        {
            u64 vA  = su.mc.V2[k][0];
            u64 vB  = su.mc.V2[k + 1][0];
            u64 mdA = su.mc.M2[k][0][0];
            u64 mdB = su.mc.M2[k + 1][0][0];
            #pragma unroll
            for (int p = 0; p < NP; p++) {
                u64 zA = fma2(mdA, d2[p][0], vA);
                u64 zB = fma2(mdB, d2[p][0], vB);
                qA[p] = fma2(zA, zA, qA[p]);
                qB[p] = fma2(zB, zB, qB[p]);
            }
        }

        // ---- Prefetch head of row 1 ----
        u64 nvA = su.mc.V2[k][1];
        u64 nvB = su.mc.V2[k + 1][1];
        ulonglong2 npA = *(const ulonglong2*)&su.mc.M2[k][1][0];
        ulonglong2 npB = *(const ulonglong2*)&su.mc.M2[k + 1][1][0];

        #pragma unroll
        for (int i = 1; i < DM; i++) {
            // Consume this row's prefetched head.
            u64 cvA = nvA, cvB = nvB;
            ulonglong2 cpA = npA, cpB = npB;

            // Prefetch next row's head (V2 + first pair).
            if (i + 1 < DM) {
                nvA = su.mc.V2[k][i + 1];
                nvB = su.mc.V2[k + 1][i + 1];
                npA = *(const ulonglong2*)&su.mc.M2[k][i + 1][0];
                npB = *(const ulonglong2*)&su.mc.M2[k + 1][i + 1][0];
            }

            u64 zA[NP], zB[NP];
            #pragma unroll
            for (int p = 0; p < NP; p++) { zA[p] = cvA; zB[p] = cvB; }

            // First pair from the prefetch registers.
            #pragma unroll
            for (int p = 0; p < NP; p++) {
                zA[p] = fma2(cpA.x, d2[p][0], zA[p]);
                zB[p] = fma2(cpB.x, d2[p][0], zB[p]);
                zA[p] = fma2(cpA.y, d2[p][1], zA[p]);
                zB[p] = fma2(cpB.y, d2[p][1], zB[p]);
            }

            // Remaining pairs: inline LDS.128 loads.
            const int npairs = (i + 1) >> 1;
            #pragma unroll
            for (int jp = 1; jp < npairs; jp++) {
                const int j = jp * 2;
                ulonglong2 mA = *(const ulonglong2*)&su.mc.M2[k][i][j];
                ulonglong2 mB = *(const ulonglong2*)&su.mc.M2[k + 1][i][j];
                #pragma unroll
                for (int p = 0; p < NP; p++) {
                    zA[p] = fma2(mA.x, d2[p][j],     zA[p]);
                    zB[p] = fma2(mB.x, d2[p][j],     zB[p]);
                    zA[p] = fma2(mA.y, d2[p][j + 1], zA[p]);
                    zB[p] = fma2(mB.y, d2[p][j + 1], zB[p]);
                }
            }
            if ((i & 1) == 0) {                     // odd row length: diagonal
                u64 mdA = su.mc.M2[k][i][i];
                u64 mdB = su.mc.M2[k + 1][i][i];
                #pragma unroll
                for (int p = 0; p < NP; p++) {
                    zA[p] = fma2(mdA, d2[p][i], zA[p]);
                    zB[p] = fma2(mdB, d2[p][i], zB[p]);
                }
            }
            #pragma unroll
            for (int p = 0; p < NP; p++) {
                qA[p] = fma2(zA[p], zA[p], qA[p]);
                qB[p] = fma2(zB[p], zB[p], qB[p]);
            }
        }

        float cA = sC[k];
        float cB = sC[k + 1];
        #pragma unroll
        for (int p = 0; p < NP; p++) {
            float a0, a1, b0, b1;
            unpack2(qA[p], a0, a1);
            unpack2(qB[p], b0, b1);
            pdf[2*p + 0] += cA * __expf(-0.5f * a0) + cB * __expf(-0.5f * b0);
            pdf[2*p + 1] += cA * __expf(-0.5f * a1) + cB * __expf(-0.5f * b1);
        }
    }

    #pragma unroll
    for (int p = 0; p < NP; p++) {
        float2 o;
        o.x = -__logf(pdf[2*p + 0]);
        o.y = -__logf(pdf[2*p + 1]);
        *(float2*)&out[base + 2 * p] = o;
    }
}

// ---------------------------------------------------------------------------
// Fused kernel: per-block coefficient prologue + balanced 14-sample batches.
// ---------------------------------------------------------------------------
__global__ __launch_bounds__(256, 1)
void gmm_fused(const float4* __restrict__ samples4,
               const float* __restrict__ samples,
               const float* __restrict__ Phi,
               const float* __restrict__ mu,
               const float* __restrict__ Sigma,
               float* __restrict__ out, int N) {
    __shared__ SU su;
    __shared__ float sC[KM];

    const int tid  = threadIdx.x;
    const int wid  = tid >> 5;
    const int lane = tid & 31;
    const int k    = wid * 2 + (lane >> 4);   // 8 warps x 2 mixtures
    const int r    = lane & 15;

    // ---- Prologue: Cholesky + triangular inverse, 2 mixtures per warp ----
    for (int j = 0; j < DM; j++)
        su.pre.L[k][r][j] = Sigma[(k * DM + r) * DM + j];
    __syncwarp();

    for (int p = 0; p < DM; p++) {
        if (r == p) {
            float s = su.pre.L[k][p][p];
            for (int q = 0; q < p; q++) s -= su.pre.L[k][p][q] * su.pre.L[k][p][q];
            su.pre.L[k][p][p] = sqrtf(s);
        }
        __syncwarp();
        if (r > p) {
            float s = su.pre.L[k][r][p];
            for (int q = 0; q < p; q++) s -= su.pre.L[k][r][q] * su.pre.L[k][p][q];
            su.pre.L[k][r][p] = s / su.pre.L[k][p][p];
        }
        __syncwarp();
    }

    // Mi = L^{-1}: lane r computes column r.
    {
        int c = r;
        for (int i = 0; i < c; i++) su.pre.Mi[k][i][c] = 0.0f;
        su.pre.Mi[k][c][c] = 1.0f / su.pre.L[k][c][c];
        for (int i = c + 1; i < DM; i++) {
            float s = 0.0f;
            for (int q = c; q < i; q++) s += su.pre.L[k][i][q] * su.pre.Mi[k][q][c];
            su.pre.Mi[k][i][c] = -s / su.pre.L[k][i][i];
        }
    }
    __syncwarp();

    // Pull row r of Mi into registers; compute v_r; lane 0 computes the norm.
    float mrow[DM];
    for (int j = 0; j < DM; j++)
        mrow[j] = (j <= r) ? su.pre.Mi[k][r][j] : 0.0f;
    float v = 0.0f;
    for (int j = 0; j <= r; j++) v += mrow[j] * mu[k * DM + j];
    if (r == 0) {
        float prodL = 1.0f;
        for (int i = 0; i < DM; i++) prodL *= su.pre.L[k][i][i];   // sqrt(det)
        sC[k] = Phi[k] / (sqrtf(2.0f * 3.14159265358979323846f) * prodL);
    }
    __syncthreads();

    // Transcribe into packed main tables (overlays the prologue scratch).
    for (int j = 0; j < DM; j++)
        su.mc.M2[k][r][j] = pack2(mrow[j], mrow[j]);
    su.mc.V2[k][r] = pack2(-v, -v);
    __syncthreads();

    // ---- Main: 14 samples per thread = NP4 + NP3 ----
    long t = (long)blockIdx.x * blockDim.x + tid;
    long base = t * SPT;
    if (base >= N) return;

    if (base + SPT <= N) {
        process_batch<4>(samples4, out, base,     su, sC);
        process_batch<3>(samples4, out, base + 8, su, sC);
    } else {
        for (long n = base; n < N; n++) {
            float d[DM];
            for (int j = 0; j < DM; j++) d[j] = samples[n * DM + j];
            float pdf = 0.0f;
            for (int kk = 0; kk < KM; kk++) {
                float quad = 0.0f;
                for (int i = 0; i < DM; i++) {
                    // V2 holds (-v, -v): use element directly (no negation).
                    float z = ((const float*)&su.mc.V2[kk][i])[0];
                    for (int j = 0; j <= i; j++)
                        z = fmaf(((const float*)&su.mc.M2[kk][i][j])[0], d[j], z);
                    quad = fmaf(z, z, quad);
                }
                pdf += sC[kk] * __expf(-0.5f * quad);
            }
            out[n] = -logf(pdf);
        }
    }
}

// ---------------------------------------------------------------------------
extern "C" void kernel_launch(void* const* d_in, const int* in_sizes, int n_in,
                              void* d_out, int out_size) {
    const float* samples = (const float*)d_in[0];
    const float* Phi     = (const float*)d_in[1];
    const float* mu      = (const float*)d_in[2];
    const float* Sigma   = (const float*)d_in[3];
    int N = in_sizes[0] / DM;

    long threads = ((long)N + SPT - 1) / SPT;
    int  blocks  = (int)((threads + 255) / 256);
    gmm_fused<<<blocks, 256>>>((const float4*)samples, samples,
                               Phi, mu, Sigma, (float*)d_out, N);
}